// round 3
// baseline (speedup 1.0000x reference)
#include <cuda_runtime.h>
#include <math_constants.h>
#include <cstdint>

// Problem geometry (fixed by the reference)
static constexpr int   B_DIM   = 64;
static constexpr int   FT      = 80 * 640;                 // 51200 elems per batch slice
static constexpr int   NTOT_I  = B_DIM * FT;               // 3,276,800 elems per channel
static constexpr long long NTOT = NTOT_I;
static constexpr int   NWORDS  = NTOT_I / 32;              // 102,400 packed words
static constexpr int   K1_BLOCKS = NTOT_I / 2048;          // 1600 (25 per batch)
static constexpr float THR     = 20.0f;

// Scratch (fully rewritten every launch -> graph-replay deterministic):
__device__ unsigned g_strain_bits[NWORDS];   // bit i == strain flat elem i is a peak
__device__ int      g_blk_c1[K1_BLOCKS];     // per-2048-elem-block strain peak count

// 8-bit peak mask for 8 consecutive elements in v0,v1 with scalar neighbors.
__device__ __forceinline__ unsigned peak_byte(float4 v0, float4 v1,
                                              float left, float right) {
    unsigned byte = 0;
    byte |= (v0.x >= THR && v0.x > left  && v0.x > v0.y) ?   1u : 0u;
    byte |= (v0.y >= THR && v0.y > v0.x && v0.y > v0.z) ?   2u : 0u;
    byte |= (v0.z >= THR && v0.z > v0.y && v0.z > v0.w) ?   4u : 0u;
    byte |= (v0.w >= THR && v0.w > v0.z && v0.w > v1.x) ?   8u : 0u;
    byte |= (v1.x >= THR && v1.x > v0.w && v1.x > v1.y) ?  16u : 0u;
    byte |= (v1.y >= THR && v1.y > v1.x && v1.y > v1.z) ?  32u : 0u;
    byte |= (v1.z >= THR && v1.z > v1.y && v1.z > v1.w) ?  64u : 0u;
    byte |= (v1.w >= THR && v1.w > v1.z && v1.w > right) ? 128u : 0u;
    return byte;
}

// ---------------------------------------------------------------------------
// Kernel 1: strain peak bitmask + per-block peak counts (c1 precompute).
// 1600 blocks x 256 threads, 8 elems/thread; each block covers 2048 flat elems
// entirely inside one batch b (FT = 25 * 2048).
// ---------------------------------------------------------------------------
__global__ void __launch_bounds__(256) strain_peaks_kernel(const float* __restrict__ x) {
    const unsigned FULL = 0xFFFFFFFFu;
    int tid  = threadIdx.x;
    int lane = tid & 31;
    int g = blockIdx.x * 2048 + tid * 8;   // fits int (< 3.28M)

    float4 v0 = *reinterpret_cast<const float4*>(x + g);
    float4 v1 = *reinterpret_cast<const float4*>(x + g + 4);

    float left  = __shfl_up_sync(FULL, v1.w, 1);
    float right = __shfl_down_sync(FULL, v0.x, 1);
    if (lane == 0)  left  = (g == 0)          ? CUDART_INF_F : __ldg(x + g - 1);
    if (lane == 31) right = (g + 8 >= NTOT_I) ? CUDART_INF_F : __ldg(x + g + 8);

    unsigned byte = peak_byte(v0, v1, left, right);

    // 4 lanes share one 32-bit word (8 bits each); OR-butterfly in the quad.
    unsigned word = byte << (8 * (lane & 3));
    word |= __shfl_xor_sync(FULL, word, 1);
    word |= __shfl_xor_sync(FULL, word, 2);
    if ((lane & 3) == 0) g_strain_bits[g >> 5] = word;

    // Block peak count -> g_blk_c1 (c1 never recomputed in the hot kernel).
    int cnt = __popc(byte);
    #pragma unroll
    for (int off = 16; off; off >>= 1) cnt += __shfl_xor_sync(FULL, cnt, off);
    __shared__ int s_cnt[8];
    if (lane == 0) s_cnt[tid >> 5] = cnt;
    __syncthreads();
    if (tid == 0) {
        int c = 0;
        #pragma unroll
        for (int k = 0; k < 8; ++k) c += s_cnt[k];
        g_blk_c1[blockIdx.x] = c;
    }
}

// ---------------------------------------------------------------------------
// Kernel 2: one 128-thread block per (aux_channel n, batch b). 16 blocks/SM
// resident (<=32 regs) -> all 2048 blocks in ONE wave, no tail quantization.
// 50 iterations of 1024 elems; single pass accumulates inter & c2; c1 comes
// from g_blk_c1 in the epilogue.
// ---------------------------------------------------------------------------
__global__ void __launch_bounds__(128, 16) iou_kernel(const float* __restrict__ aux,
                                                      float* __restrict__ out,
                                                      int half) {
    const unsigned FULL = 0xFFFFFFFFu;
    int pair = blockIdx.x;          // n * 64 + b  (matches flat output order)
    int n    = pair >> 6;
    int b    = pair & 63;
    const float* qa = aux + (long long)n * NTOT;   // 64-bit once, outside loop
    int gbase = b * FT;                            // 32-bit inside channel

    int tid  = threadIdx.x;
    int lane = tid & 31;

    int inter = 0, c2 = 0;

    // 51200 / (128 threads * 8 elems) = 50 iterations
    #pragma unroll 2
    for (int it = 0; it < FT / 1024; ++it) {
        int g = gbase + it * 1024 + tid * 8;

        float4  v0 = *reinterpret_cast<const float4*>(qa + g);
        float4  v1 = *reinterpret_cast<const float4*>(qa + g + 4);
        unsigned sw = g_strain_bits[g >> 5];       // L2-resident, quad-broadcast

        float left  = __shfl_up_sync(FULL, v1.w, 1);
        float right = __shfl_down_sync(FULL, v0.x, 1);
        if (lane == 0)  left  = (g == 0)          ? CUDART_INF_F : __ldg(qa + g - 1);
        if (lane == 31) right = (g + 8 >= NTOT_I) ? CUDART_INF_F : __ldg(qa + g + 8);

        unsigned byte  = peak_byte(v0, v1, left, right);
        unsigned sbyte = (sw >> (8 * (lane & 3))) & 0xFFu;
        inter += __popc(byte & sbyte);
        c2    += __popc(byte);
    }

    // Warp reduce (4 warps)
    #pragma unroll
    for (int off = 16; off; off >>= 1) {
        inter += __shfl_xor_sync(FULL, inter, off);
        c2    += __shfl_xor_sync(FULL, c2,    off);
    }
    __shared__ int s_i[4], s_2[4];
    if (lane == 0) { s_i[tid >> 5] = inter; s_2[tid >> 5] = c2; }
    __syncthreads();

    if (tid < 32) {
        int I  = (tid < 4)  ? s_i[tid] : 0;
        int C2 = (tid < 4)  ? s_2[tid] : 0;
        int C1 = (tid < 25) ? g_blk_c1[b * 25 + tid] : 0;   // L2 hits
        #pragma unroll
        for (int off = 16; off; off >>= 1) {
            I  += __shfl_xor_sync(FULL, I,  off);
            C2 += __shfl_xor_sync(FULL, C2, off);
            C1 += __shfl_xor_sync(FULL, C1, off);
        }
        if (tid == 0) {
            float u = (float)(C1 + C2 - I);
            float jac, ratio;
            if (u == 0.0f) {               // inter==0 && union==0 -> both 1.0
                jac = 1.0f; ratio = 1.0f;
            } else {
                jac   = (float)I / u;
                ratio = (C1 == 0) ? 0.0f   // nan_to_num(0/0) -> 0 (I<=C1 so I==0 here)
                                  : (float)I / (float)C1;
            }
            out[pair]        = jac;        // iou half
            out[half + pair] = ratio;      // corr half
        }
    }
}

extern "C" void kernel_launch(void* const* d_in, const int* in_sizes, int n_in,
                              void* d_out, int out_size) {
    const float* strain = (const float*)d_in[0];   // qt_strain [64,80,640]
    const float* aux    = (const float*)d_in[1];   // qt_aux [32,64,80,640]
    float* out          = (float*)d_out;           // [iou(2048) | corr(2048)]

    strain_peaks_kernel<<<K1_BLOCKS, 256>>>(strain);
    iou_kernel<<<32 * B_DIM, 128>>>(aux, out, out_size / 2);
}